// round 2
// baseline (speedup 1.0000x reference)
#include <cuda_runtime.h>
#include <cuda_fp16.h>
#include <cstdint>

// y = x @ (scale*(Wq - zp))^T + bias
// x [8192, 4096] fp32, Wq [4096, 4096] i32, out [8192, 4096] fp32.
#define M_TOTAL 8192
#define K_TOTAL 4096
#define N_TOTAL 4096

static constexpr int TM = 128;
static constexpr int TN = 128;
static constexpr int KC = 64;            // k-chunk: 64 fp16 = 128B rows (SW128 atom)
static constexpr int NK = K_TOTAL / KC;  // 64
static constexpr int STAGES = 4;
static constexpr int TILE_BYTES = TM * KC * 2;          // 16384 per operand tile
static constexpr int STAGE_BYTES = 2 * TILE_BYTES;      // A + B = 32768
static constexpr int SMEM_BYTES = STAGES * STAGE_BYTES; // 131072

// ---------------- scratch (device globals: allocation-free) ----------------
__device__ __align__(1024) __half g_A[(size_t)M_TOTAL * K_TOTAL];  // 64 MB
__device__ __align__(1024) __half g_B[(size_t)N_TOTAL * K_TOTAL];  // 32 MB

// ---------------- helpers ----------------
__device__ __forceinline__ uint32_t smem_u32(const void* p) {
    uint32_t a;
    asm("{ .reg .u64 t; cvta.to.shared.u64 t, %1; cvt.u32.u64 %0, t; }" : "=r"(a) : "l"(p));
    return a;
}
__device__ __forceinline__ uint32_t sw128(uint32_t off) {
    return off ^ ((off >> 3) & 0x70);
}
#define CP_ASYNC16(dst, src) \
    asm volatile("cp.async.cg.shared.global [%0], [%1], 16;" :: "r"(dst), "l"(src) : "memory")
#define CP_COMMIT() asm volatile("cp.async.commit_group;" ::: "memory")
#define CP_WAIT2()  asm volatile("cp.async.wait_group 2;" ::: "memory")

__device__ __forceinline__ void ldsm_x4(uint32_t& r0, uint32_t& r1, uint32_t& r2, uint32_t& r3,
                                        uint32_t addr) {
    asm volatile("ldmatrix.sync.aligned.m8n8.x4.shared.b16 {%0,%1,%2,%3}, [%4];"
                 : "=r"(r0), "=r"(r1), "=r"(r2), "=r"(r3) : "r"(addr));
}
__device__ __forceinline__ void mma16816(float* c, uint32_t a0, uint32_t a1, uint32_t a2,
                                         uint32_t a3, uint32_t b0, uint32_t b1) {
    asm volatile(
        "mma.sync.aligned.m16n8k16.row.col.f32.f16.f16.f32 "
        "{%0,%1,%2,%3}, {%4,%5,%6,%7}, {%8,%9}, {%0,%1,%2,%3};"
        : "+f"(c[0]), "+f"(c[1]), "+f"(c[2]), "+f"(c[3])
        : "r"(a0), "r"(a1), "r"(a2), "r"(a3), "r"(b0), "r"(b1));
}

// ---------------- prep kernels ----------------
__global__ void convert_w_kernel(const int* __restrict__ q, const float* __restrict__ zp_p) {
    float zp = *zp_p;
    size_t i = ((size_t)blockIdx.x * blockDim.x + threadIdx.x) * 4;
    if (i >= (size_t)N_TOTAL * K_TOTAL) return;
    int4 v = *reinterpret_cast<const int4*>(q + i);
    __half2 p0, p1;
    p0.x = __float2half_rn((float)v.x - zp);
    p0.y = __float2half_rn((float)v.y - zp);
    p1.x = __float2half_rn((float)v.z - zp);
    p1.y = __float2half_rn((float)v.w - zp);
    *reinterpret_cast<__half2*>(&g_B[i])     = p0;
    *reinterpret_cast<__half2*>(&g_B[i + 2]) = p1;
}

__global__ void convert_x_kernel(const float* __restrict__ x) {
    size_t i = ((size_t)blockIdx.x * blockDim.x + threadIdx.x) * 4;
    if (i >= (size_t)M_TOTAL * K_TOTAL) return;
    float4 v = *reinterpret_cast<const float4*>(x + i);
    __half2 h0 = __floats2half2_rn(v.x, v.y);
    __half2 h1 = __floats2half2_rn(v.z, v.w);
    *reinterpret_cast<__half2*>(&g_A[i])     = h0;
    *reinterpret_cast<__half2*>(&g_A[i + 2]) = h1;
}

// ---------------- GEMM: 128x128 CTA tile, 8 warps (2m x 4n), 64x32 warp tile ----------------
__global__ void __launch_bounds__(256, 1)
gemm_kernel(const float* __restrict__ bias, const float* __restrict__ scale_p,
            float* __restrict__ out) {
    extern __shared__ char smem[];
    const uint32_t sb = smem_u32(smem);
    const int tid = threadIdx.x;
    const int wid = tid >> 5;
    const int lane = tid & 31;

    // Supertiled CTA mapping: groups of 8 N-tiles across all M-tiles (L2 reuse)
    constexpr int MTILES = M_TOTAL / TM;  // 64
    constexpr int GROUPN = 8;
    constexpr int PER = MTILES * GROUPN;  // 512
    const int bid = blockIdx.x;
    const int grp = bid / PER;
    const int rem = bid % PER;
    const int m0 = (rem / GROUPN) * TM;
    const int n0 = (grp * GROUPN + (rem % GROUPN)) * TN;

    // warp tile: wm in {0,1} -> 64 rows, wn in {0..3} -> 32 cols
    const int wm = wid >> 2;
    const int wn = wid & 3;

    // ---- cp.async load mapping: 8 chunks of 16B per 128B row, 32 rows/pass, 4 passes ----
    const int chunk = tid & 7;
    const int row0 = tid >> 3;  // 0..31
    uint32_t dst_off[4];
#pragma unroll
    for (int j = 0; j < 4; j++)
        dst_off[j] = sw128((uint32_t)(row0 + 32 * j) * 128u + (uint32_t)chunk * 16u);

    const __half* gA = g_A + (size_t)m0 * K_TOTAL + chunk * 8;
    const __half* gB = g_B + (size_t)n0 * K_TOTAL + chunk * 8;

    auto load_stage = [&](int kc, int buf) {
        const uint32_t tb = sb + (uint32_t)buf * STAGE_BYTES;
        const size_t koff = (size_t)kc * KC;
#pragma unroll
        for (int j = 0; j < 4; j++) {
            const size_t roff = (size_t)(row0 + 32 * j) * K_TOTAL + koff;
            CP_ASYNC16(tb + dst_off[j], gA + roff);
            CP_ASYNC16(tb + TILE_BYTES + dst_off[j], gB + roff);
        }
        CP_COMMIT();
    };

    // ---- ldmatrix source addresses (per ks they shift by 32B in swizzled space) ----
    // A: 4 m16 tiles; lane -> mat = lane>>3, r = lane&7
    //    row = wm*64 + tm*16 + r + ((mat&1)<<3), col16 base + ((mat>>1)<<3)
    const int lmat = lane >> 3;
    const int lrow = lane & 7;
    uint32_t a_off[4];
#pragma unroll
    for (int tm = 0; tm < 4; tm++) {
        uint32_t r = (uint32_t)(wm * 64 + tm * 16 + lrow + ((lmat & 1) << 3));
        uint32_t c = (uint32_t)((lmat >> 1) << 3);
        a_off[tm] = sw128(r * 128u + c * 2u);
    }
    // B: 2 n16-pairs; row(n) = wn*32 + p*16 + r + ((mat>>1)<<3), col(k) = ((mat&1)<<3)
    uint32_t b_off[2];
#pragma unroll
    for (int p = 0; p < 2; p++) {
        uint32_t r = (uint32_t)(wn * 32 + p * 16 + lrow + ((lmat >> 1) << 3));
        uint32_t c = (uint32_t)((lmat & 1) << 3);
        b_off[p] = sw128(r * 128u + c * 2u) + TILE_BYTES;
    }

    float acc[4][4][4];
#pragma unroll
    for (int i = 0; i < 4; i++)
#pragma unroll
        for (int j = 0; j < 4; j++)
#pragma unroll
            for (int k = 0; k < 4; k++) acc[i][j][k] = 0.f;

    // ---- prologue: fill 3 of 4 stages ----
    load_stage(0, 0);
    load_stage(1, 1);
    load_stage(2, 2);

    for (int kc = 0; kc < NK; ++kc) {
        CP_WAIT2();
        __syncthreads();
        if (kc + 3 < NK) load_stage(kc + 3, (kc + 3) & 3);
        else CP_COMMIT();  // keep wait_group accounting

        const uint32_t tb = sb + (uint32_t)(kc & 3) * STAGE_BYTES;
#pragma unroll
        for (int ks = 0; ks < 4; ++ks) {
            // ks*16 halfs = 32 bytes; sw128 XOR-folds bits[6:4], and +32B only touches
            // bit5/bit6 of the SAME row, so we must re-swizzle: offset delta within row.
            const uint32_t kbyte = (uint32_t)ks * 32u;
            uint32_t a0[4], a1[4], a2[4], a3[4];
#pragma unroll
            for (int tm = 0; tm < 4; tm++) {
                uint32_t ad = tb + (a_off[tm] ^ kbyte);  // kbyte only has bits 5..6 -> XOR == add within swizzle
                ldsm_x4(a0[tm], a1[tm], a2[tm], a3[tm], ad);
            }
            uint32_t b0[4], b1[4];
#pragma unroll
            for (int p = 0; p < 2; p++) {
                uint32_t bd = tb + (b_off[p] ^ kbyte);
                uint32_t r0, r1, r2, r3;
                ldsm_x4(r0, r1, r2, r3, bd);
                b0[2 * p] = r0; b1[2 * p] = r1;
                b0[2 * p + 1] = r2; b1[2 * p + 1] = r3;
            }
#pragma unroll
            for (int tm = 0; tm < 4; tm++)
#pragma unroll
                for (int tn = 0; tn < 4; tn++)
                    mma16816(acc[tm][tn], a0[tm], a1[tm], a2[tm], a3[tm], b0[tn], b1[tn]);
        }
        __syncthreads();
    }

    // ---- epilogue: out = scale*acc + bias ----
    const float scale = *scale_p;
    const int r_base = m0 + wm * 64 + (lane >> 2);
    const int c_base = n0 + wn * 32 + (lane & 3) * 2;
#pragma unroll
    for (int tm = 0; tm < 4; tm++) {
#pragma unroll
        for (int tn = 0; tn < 4; tn++) {
            const int col = c_base + tn * 8;
            const float2 bv = *reinterpret_cast<const float2*>(bias + col);
            const int row = r_base + tm * 16;
            float2 o0, o1;
            o0.x = fmaf(scale, acc[tm][tn][0], bv.x);
            o0.y = fmaf(scale, acc[tm][tn][1], bv.y);
            o1.x = fmaf(scale, acc[tm][tn][2], bv.x);
            o1.y = fmaf(scale, acc[tm][tn][3], bv.y);
            *reinterpret_cast<float2*>(out + (size_t)row * N_TOTAL + col) = o0;
            *reinterpret_cast<float2*>(out + (size_t)(row + 8) * N_TOTAL + col) = o1;
        }
    }
}

// ---------------- launch ----------------
extern "C" void kernel_launch(void* const* d_in, const int* in_sizes, int n_in,
                              void* d_out, int out_size) {
    const float* x     = (const float*)d_in[0];
    const int*   wq    = (const int*)  d_in[1];
    const float* bias  = (const float*)d_in[2];
    const float* scale = (const float*)d_in[3];
    const float* zp    = (const float*)d_in[4];
    float* out = (float*)d_out;

    cudaFuncSetAttribute(gemm_kernel, cudaFuncAttributeMaxDynamicSharedMemorySize, SMEM_BYTES);

    {
        const size_t n4 = (size_t)N_TOTAL * K_TOTAL / 4;
        convert_w_kernel<<<(unsigned)((n4 + 255) / 256), 256>>>(wq, zp);
    }
    {
        const size_t n4 = (size_t)M_TOTAL * K_TOTAL / 4;
        convert_x_kernel<<<(unsigned)((n4 + 255) / 256), 256>>>(x);
    }
    {
        const int grid = (M_TOTAL / TM) * (N_TOTAL / TN);  // 2048
        gemm_kernel<<<grid, 256, SMEM_BYTES>>>(bias, scale, out);
    }
}

// round 6
// speedup vs baseline: 1.0754x; 1.0754x over previous
#include <cuda_runtime.h>
#include <cuda_fp16.h>
#include <cstdint>

// y = x @ (scale*(Wq - zp))^T + bias
// x [8192, 4096] fp32, Wq [4096, 4096] i32, out [8192, 4096] fp32.
#define M_TOTAL 8192
#define K_TOTAL 4096
#define N_TOTAL 4096

static constexpr int TM = 128;
static constexpr int TN = 128;
static constexpr int KC = 128;           // k-chunk: 2 SW128 column-blocks of 64 halfs
static constexpr int NK = K_TOTAL / KC;  // 32
static constexpr int STAGES = 3;
static constexpr int BLK_BYTES = 128 * 64 * 2;          // 16384: one 128-row x 64-half block
static constexpr int OP_BYTES  = 2 * BLK_BYTES;         // 32768 per operand per stage
static constexpr int STAGE_BYTES = 2 * OP_BYTES;        // A + B = 65536
static constexpr int SMEM_BYTES = STAGES * STAGE_BYTES; // 196608

// ---------------- scratch (device globals: allocation-free) ----------------
__device__ __align__(1024) __half g_A[(size_t)M_TOTAL * K_TOTAL];  // 64 MB
__device__ __align__(1024) __half g_B[(size_t)N_TOTAL * K_TOTAL];  // 32 MB

// ---------------- helpers ----------------
__device__ __forceinline__ uint32_t smem_u32(const void* p) {
    uint32_t a;
    asm("{ .reg .u64 t; cvta.to.shared.u64 t, %1; cvt.u32.u64 %0, t; }" : "=r"(a) : "l"(p));
    return a;
}
__device__ __forceinline__ uint32_t sw128(uint32_t off) {
    return off ^ ((off >> 3) & 0x70);
}
#define CP_ASYNC16(dst, src) \
    asm volatile("cp.async.cg.shared.global [%0], [%1], 16;" :: "r"(dst), "l"(src) : "memory")
#define CP_COMMIT() asm volatile("cp.async.commit_group;" ::: "memory")
#define CP_WAIT1()  asm volatile("cp.async.wait_group 1;" ::: "memory")

__device__ __forceinline__ void ldsm_x4(uint32_t& r0, uint32_t& r1, uint32_t& r2, uint32_t& r3,
                                        uint32_t addr) {
    asm volatile("ldmatrix.sync.aligned.m8n8.x4.shared.b16 {%0,%1,%2,%3}, [%4];"
                 : "=r"(r0), "=r"(r1), "=r"(r2), "=r"(r3) : "r"(addr));
}
__device__ __forceinline__ void mma16816(float* c, uint32_t a0, uint32_t a1, uint32_t a2,
                                         uint32_t a3, uint32_t b0, uint32_t b1) {
    asm volatile(
        "mma.sync.aligned.m16n8k16.row.col.f32.f16.f16.f32 "
        "{%0,%1,%2,%3}, {%4,%5,%6,%7}, {%8,%9}, {%0,%1,%2,%3};"
        : "+f"(c[0]), "+f"(c[1]), "+f"(c[2]), "+f"(c[3])
        : "r"(a0), "r"(a1), "r"(a2), "r"(a3), "r"(b0), "r"(b1));
}

// ---------------- prep kernels ----------------
__global__ void convert_w_kernel(const int* __restrict__ q, const float* __restrict__ zp_p) {
    float zp = *zp_p;
    size_t i = ((size_t)blockIdx.x * blockDim.x + threadIdx.x) * 4;
    if (i >= (size_t)N_TOTAL * K_TOTAL) return;
    int4 v = *reinterpret_cast<const int4*>(q + i);
    __half2 p0, p1;
    p0.x = __float2half_rn((float)v.x - zp);
    p0.y = __float2half_rn((float)v.y - zp);
    p1.x = __float2half_rn((float)v.z - zp);
    p1.y = __float2half_rn((float)v.w - zp);
    *reinterpret_cast<__half2*>(&g_B[i])     = p0;
    *reinterpret_cast<__half2*>(&g_B[i + 2]) = p1;
}

__global__ void convert_x_kernel(const float* __restrict__ x) {
    size_t i = ((size_t)blockIdx.x * blockDim.x + threadIdx.x) * 4;
    if (i >= (size_t)M_TOTAL * K_TOTAL) return;
    float4 v = *reinterpret_cast<const float4*>(x + i);
    __half2 h0 = __floats2half2_rn(v.x, v.y);
    __half2 h1 = __floats2half2_rn(v.z, v.w);
    *reinterpret_cast<__half2*>(&g_A[i])     = h0;
    *reinterpret_cast<__half2*>(&g_A[i + 2]) = h1;
}

// ---------------- GEMM: 128x128 CTA tile, 8 warps (2m x 4n), 64x32 warp tile ----------------
__global__ void __launch_bounds__(256, 1)
gemm_kernel(const float* __restrict__ bias, const float* __restrict__ scale_p,
            float* __restrict__ out) {
    extern __shared__ char smem[];
    const uint32_t sb = smem_u32(smem);
    const int tid = threadIdx.x;
    const int wid = tid >> 5;
    const int lane = tid & 31;

    // Supertiled CTA mapping: groups of 8 N-tiles across all M-tiles (L2 reuse)
    constexpr int MTILES = M_TOTAL / TM;  // 64
    constexpr int GROUPN = 8;
    constexpr int PER = MTILES * GROUPN;  // 512
    const int bid = blockIdx.x;
    const int grp = bid / PER;
    const int rem = bid % PER;
    const int m0 = (rem / GROUPN) * TM;
    const int n0 = (grp * GROUPN + (rem % GROUPN)) * TN;

    const int wm = wid >> 2;   // 0..1  -> 64 rows
    const int wn = wid & 3;    // 0..3  -> 32 cols

    // ---- cp.async mapping: 8x16B chunks per 128B row, 32 rows/pass, 4 passes/block ----
    const int chunk = tid & 7;
    const int row0 = tid >> 3;  // 0..31
    uint32_t dst_off[4];
#pragma unroll
    for (int j = 0; j < 4; j++)
        dst_off[j] = sw128((uint32_t)(row0 + 32 * j) * 128u + (uint32_t)chunk * 16u);

    const __half* gA = g_A + (size_t)m0 * K_TOTAL + chunk * 8;
    const __half* gB = g_B + (size_t)n0 * K_TOTAL + chunk * 8;

    auto load_stage = [&](int kc, int buf) {
        const uint32_t tb = sb + (uint32_t)buf * STAGE_BYTES;
        const size_t koff = (size_t)kc * KC;
#pragma unroll
        for (int kb = 0; kb < 2; kb++) {
            const size_t kb_off = koff + kb * 64;
            const uint32_t sblk = tb + (uint32_t)kb * BLK_BYTES;
#pragma unroll
            for (int j = 0; j < 4; j++) {
                const size_t roff = (size_t)(row0 + 32 * j) * K_TOTAL + kb_off;
                CP_ASYNC16(sblk + dst_off[j],            gA + roff);
                CP_ASYNC16(sblk + OP_BYTES + dst_off[j], gB + roff);
            }
        }
        CP_COMMIT();
    };

    // ---- ldmatrix lane addressing (within one 16KB block) ----
    const int lmat = lane >> 3;
    const int lrow = lane & 7;
    uint32_t a_off[4];
#pragma unroll
    for (int tm = 0; tm < 4; tm++) {
        uint32_t r = (uint32_t)(wm * 64 + tm * 16 + lrow + ((lmat & 1) << 3));
        uint32_t c = (uint32_t)((lmat >> 1) << 3);
        a_off[tm] = sw128(r * 128u + c * 2u);
    }
    uint32_t b_off[2];
#pragma unroll
    for (int p = 0; p < 2; p++) {
        uint32_t r = (uint32_t)(wn * 32 + p * 16 + lrow + ((lmat >> 1) << 3));
        uint32_t c = (uint32_t)((lmat & 1) << 3);
        b_off[p] = sw128(r * 128u + c * 2u);
    }

    float acc[4][4][4];
#pragma unroll
    for (int i = 0; i < 4; i++)
#pragma unroll
        for (int j = 0; j < 4; j++)
#pragma unroll
            for (int k = 0; k < 4; k++) acc[i][j][k] = 0.f;

    // register double buffers for ldmatrix fragments
    uint32_t ra0[2][4], ra1[2][4], ra2[2][4], ra3[2][4], rb0[2][4], rb1[2][4];

    auto ldsm_ks = [&](int dbuf, uint32_t tb, int ks) {
        const int kb = ks >> 2;
        const uint32_t kbyte = (uint32_t)(ks & 3) * 32u;  // bits 5..6 only; XOR == add under sw128
        const uint32_t abase = tb + (uint32_t)kb * BLK_BYTES;
        const uint32_t bbase = abase + OP_BYTES;
#pragma unroll
        for (int tm = 0; tm < 4; tm++)
            ldsm_x4(ra0[dbuf][tm], ra1[dbuf][tm], ra2[dbuf][tm], ra3[dbuf][tm],
                    abase + (a_off[tm] ^ kbyte));
#pragma unroll
        for (int p = 0; p < 2; p++) {
            uint32_t r0, r1, r2, r3;
            ldsm_x4(r0, r1, r2, r3, bbase + (b_off[p] ^ kbyte));
            rb0[dbuf][2 * p] = r0;     rb1[dbuf][2 * p] = r1;
            rb0[dbuf][2 * p + 1] = r2; rb1[dbuf][2 * p + 1] = r3;
        }
    };

    // ---- prologue: fill 2 of 3 stages ----
    load_stage(0, 0);
    load_stage(1, 1);

    for (int kc = 0; kc < NK; ++kc) {
        CP_WAIT1();            // stage kc resident
        __syncthreads();       // also: everyone done reading buffer (kc+2)%3 (iter kc-1)
        if (kc + 2 < NK) load_stage(kc + 2, (kc + 2) % 3);
        else CP_COMMIT();      // keep wait_group accounting

        const uint32_t tb = sb + (uint32_t)(kc % 3) * STAGE_BYTES;
        ldsm_ks(0, tb, 0);
#pragma unroll
        for (int ks = 0; ks < 8; ++ks) {
            const int cur = ks & 1;
            if (ks < 7) ldsm_ks(cur ^ 1, tb, ks + 1);
#pragma unroll
            for (int tm = 0; tm < 4; tm++)
#pragma unroll
                for (int tn = 0; tn < 4; tn++)
                    mma16816(acc[tm][tn], ra0[cur][tm], ra1[cur][tm], ra2[cur][tm],
                             ra3[cur][tm], rb0[cur][tn], rb1[cur][tn]);
        }
    }

    // ---- epilogue: out = scale*acc + bias ----
    const float scale = *scale_p;
    const int r_base = m0 + wm * 64 + (lane >> 2);
    const int c_base = n0 + wn * 32 + (lane & 3) * 2;
#pragma unroll
    for (int tm = 0; tm < 4; tm++) {
#pragma unroll
        for (int tn = 0; tn < 4; tn++) {
            const int col = c_base + tn * 8;
            const float2 bv = *reinterpret_cast<const float2*>(bias + col);
            const int row = r_base + tm * 16;
            float2 o0, o1;
            o0.x = fmaf(scale, acc[tm][tn][0], bv.x);
            o0.y = fmaf(scale, acc[tm][tn][1], bv.y);
            o1.x = fmaf(scale, acc[tm][tn][2], bv.x);
            o1.y = fmaf(scale, acc[tm][tn][3], bv.y);
            *reinterpret_cast<float2*>(out + (size_t)row * N_TOTAL + col) = o0;
            *reinterpret_cast<float2*>(out + (size_t)(row + 8) * N_TOTAL + col) = o1;
        }
    }
}

// ---------------- launch ----------------
extern "C" void kernel_launch(void* const* d_in, const int* in_sizes, int n_in,
                              void* d_out, int out_size) {
    const float* x     = (const float*)d_in[0];
    const int*   wq    = (const int*)  d_in[1];
    const float* bias  = (const float*)d_in[2];
    const float* scale = (const float*)d_in[3];
    const float* zp    = (const float*)d_in[4];
    float* out = (float*)d_out;

    cudaFuncSetAttribute(gemm_kernel, cudaFuncAttributeMaxDynamicSharedMemorySize, SMEM_BYTES);

    {
        const size_t n4 = (size_t)N_TOTAL * K_TOTAL / 4;
        convert_w_kernel<<<(unsigned)((n4 + 255) / 256), 256>>>(wq, zp);
    }
    {
        const size_t n4 = (size_t)M_TOTAL * K_TOTAL / 4;
        convert_x_kernel<<<(unsigned)((n4 + 255) / 256), 256>>>(x);
    }
    {
        const int grid = (M_TOTAL / TM) * (N_TOTAL / TN);  // 2048
        gemm_kernel<<<grid, 256, SMEM_BYTES>>>(bias, scale, out);
    }
}

// round 7
// speedup vs baseline: 1.1764x; 1.0938x over previous
#include <cuda_runtime.h>
#include <cuda_fp16.h>
#include <cstdint>

// y = x @ (scale*(Wq - zp))^T + bias
// x [8192, 4096] fp32, Wq [4096, 4096] i32, out [8192, 4096] fp32.
#define M_TOTAL 8192
#define K_TOTAL 4096
#define N_TOTAL 4096

static constexpr int TM = 128;
static constexpr int TN = 256;
static constexpr int KC = 64;            // k-chunk: one SW128 column-block (64 halfs)
static constexpr int NK = K_TOTAL / KC;  // 64
static constexpr int STAGES = 4;
static constexpr int A_BYTES = TM * KC * 2;             // 16384
static constexpr int B_BYTES = TN * KC * 2;             // 32768
static constexpr int STAGE_BYTES = A_BYTES + B_BYTES;   // 49152
static constexpr int SMEM_BYTES = STAGES * STAGE_BYTES; // 196608

// ---------------- scratch (device globals: allocation-free) ----------------
__device__ __align__(1024) __half g_A[(size_t)M_TOTAL * K_TOTAL];  // 64 MB
__device__ __align__(1024) __half g_B[(size_t)N_TOTAL * K_TOTAL];  // 32 MB

// ---------------- helpers ----------------
__device__ __forceinline__ uint32_t smem_u32(const void* p) {
    uint32_t a;
    asm("{ .reg .u64 t; cvta.to.shared.u64 t, %1; cvt.u32.u64 %0, t; }" : "=r"(a) : "l"(p));
    return a;
}
__device__ __forceinline__ uint32_t sw128(uint32_t off) {
    return off ^ ((off >> 3) & 0x70);
}
#define CP_ASYNC16(dst, src) \
    asm volatile("cp.async.cg.shared.global [%0], [%1], 16;" :: "r"(dst), "l"(src) : "memory")
#define CP_COMMIT() asm volatile("cp.async.commit_group;" ::: "memory")
#define CP_WAIT2()  asm volatile("cp.async.wait_group 2;" ::: "memory")

__device__ __forceinline__ void ldsm_x4(uint32_t& r0, uint32_t& r1, uint32_t& r2, uint32_t& r3,
                                        uint32_t addr) {
    asm volatile("ldmatrix.sync.aligned.m8n8.x4.shared.b16 {%0,%1,%2,%3}, [%4];"
                 : "=r"(r0), "=r"(r1), "=r"(r2), "=r"(r3) : "r"(addr));
}
__device__ __forceinline__ void mma16816(float* c, uint32_t a0, uint32_t a1, uint32_t a2,
                                         uint32_t a3, uint32_t b0, uint32_t b1) {
    asm volatile(
        "mma.sync.aligned.m16n8k16.row.col.f32.f16.f16.f32 "
        "{%0,%1,%2,%3}, {%4,%5,%6,%7}, {%8,%9}, {%0,%1,%2,%3};"
        : "+f"(c[0]), "+f"(c[1]), "+f"(c[2]), "+f"(c[3])
        : "r"(a0), "r"(a1), "r"(a2), "r"(a3), "r"(b0), "r"(b1));
}

// ---------------- prep kernels ----------------
__global__ void convert_w_kernel(const int* __restrict__ q, const float* __restrict__ zp_p) {
    float zp = *zp_p;
    size_t i = ((size_t)blockIdx.x * blockDim.x + threadIdx.x) * 4;
    if (i >= (size_t)N_TOTAL * K_TOTAL) return;
    int4 v = *reinterpret_cast<const int4*>(q + i);
    __half2 p0, p1;
    p0.x = __float2half_rn((float)v.x - zp);
    p0.y = __float2half_rn((float)v.y - zp);
    p1.x = __float2half_rn((float)v.z - zp);
    p1.y = __float2half_rn((float)v.w - zp);
    *reinterpret_cast<__half2*>(&g_B[i])     = p0;
    *reinterpret_cast<__half2*>(&g_B[i + 2]) = p1;
}

__global__ void convert_x_kernel(const float* __restrict__ x) {
    size_t i = ((size_t)blockIdx.x * blockDim.x + threadIdx.x) * 4;
    if (i >= (size_t)M_TOTAL * K_TOTAL) return;
    float4 v = *reinterpret_cast<const float4*>(x + i);
    __half2 h0 = __floats2half2_rn(v.x, v.y);
    __half2 h1 = __floats2half2_rn(v.z, v.w);
    *reinterpret_cast<__half2*>(&g_A[i])     = h0;
    *reinterpret_cast<__half2*>(&g_A[i + 2]) = h1;
}

// ---------------- GEMM: 128x256 CTA tile, 8 warps (2m x 4n), 64x64 warp tile ----------------
__global__ void __launch_bounds__(256, 1)
gemm_kernel(const float* __restrict__ bias, const float* __restrict__ scale_p,
            float* __restrict__ out) {
    extern __shared__ char smem[];
    const uint32_t sb = smem_u32(smem);
    const int tid = threadIdx.x;
    const int wid = tid >> 5;
    const int lane = tid & 31;

    // Supertiled CTA mapping: groups of 8 N-tiles across all M-tiles (L2 reuse)
    constexpr int MTILES = M_TOTAL / TM;  // 64
    constexpr int GROUPN = 8;
    constexpr int PER = MTILES * GROUPN;  // 512
    const int bid = blockIdx.x;
    const int grp = bid / PER;            // 0..1
    const int rem = bid % PER;
    const int m0 = (rem / GROUPN) * TM;
    const int n0 = (grp * GROUPN + (rem % GROUPN)) * TN;

    const int wm = wid >> 2;   // 0..1 -> 64 rows
    const int wn = wid & 3;    // 0..3 -> 64 cols

    // ---- cp.async mapping: 8x16B chunks per 128B row, 32 rows/pass ----
    const int chunk = tid & 7;
    const int row0 = tid >> 3;  // 0..31
    uint32_t dstA[4], dstB[8];
#pragma unroll
    for (int j = 0; j < 4; j++)
        dstA[j] = sw128((uint32_t)(row0 + 32 * j) * 128u + (uint32_t)chunk * 16u);
#pragma unroll
    for (int j = 0; j < 8; j++)
        dstB[j] = sw128((uint32_t)(row0 + 32 * j) * 128u + (uint32_t)chunk * 16u) + A_BYTES;

    const __half* gA = g_A + (size_t)m0 * K_TOTAL + chunk * 8;
    const __half* gB = g_B + (size_t)n0 * K_TOTAL + chunk * 8;

    auto load_stage = [&](int kc, int buf) {
        const uint32_t tb = sb + (uint32_t)buf * STAGE_BYTES;
        const size_t koff = (size_t)kc * KC;
#pragma unroll
        for (int j = 0; j < 4; j++)
            CP_ASYNC16(tb + dstA[j], gA + (size_t)(row0 + 32 * j) * K_TOTAL + koff);
#pragma unroll
        for (int j = 0; j < 8; j++)
            CP_ASYNC16(tb + dstB[j], gB + (size_t)(row0 + 32 * j) * K_TOTAL + koff);
        CP_COMMIT();
    };

    // ---- ldmatrix lane addressing ----
    const int lmat = lane >> 3;
    const int lrow = lane & 7;
    uint32_t a_off[4];
#pragma unroll
    for (int tm = 0; tm < 4; tm++) {
        uint32_t r = (uint32_t)(wm * 64 + tm * 16 + lrow + ((lmat & 1) << 3));
        uint32_t c = (uint32_t)((lmat >> 1) << 3);
        a_off[tm] = sw128(r * 128u + c * 2u);
    }
    uint32_t b_off[4];
#pragma unroll
    for (int p = 0; p < 4; p++) {
        uint32_t r = (uint32_t)(wn * 64 + p * 16 + lrow + ((lmat >> 1) << 3));
        uint32_t c = (uint32_t)((lmat & 1) << 3);
        b_off[p] = sw128(r * 128u + c * 2u) + A_BYTES;
    }

    float acc[4][8][4];
#pragma unroll
    for (int i = 0; i < 4; i++)
#pragma unroll
        for (int j = 0; j < 8; j++)
#pragma unroll
            for (int k = 0; k < 4; k++) acc[i][j][k] = 0.f;

    // register double buffers for ldmatrix fragments
    uint32_t ra0[2][4], ra1[2][4], ra2[2][4], ra3[2][4], rb0[2][8], rb1[2][8];

    auto ldsm_ks = [&](int dbuf, uint32_t tb, int ks) {
        const uint32_t kbyte = (uint32_t)ks * 32u;  // bits 5..6 only; XOR == add under sw128
#pragma unroll
        for (int tm = 0; tm < 4; tm++)
            ldsm_x4(ra0[dbuf][tm], ra1[dbuf][tm], ra2[dbuf][tm], ra3[dbuf][tm],
                    tb + (a_off[tm] ^ kbyte));
#pragma unroll
        for (int p = 0; p < 4; p++) {
            uint32_t r0, r1, r2, r3;
            ldsm_x4(r0, r1, r2, r3, tb + (b_off[p] ^ kbyte));
            rb0[dbuf][2 * p] = r0;     rb1[dbuf][2 * p] = r1;
            rb0[dbuf][2 * p + 1] = r2; rb1[dbuf][2 * p + 1] = r3;
        }
    };

    // ---- prologue: fill 3 of 4 stages ----
    load_stage(0, 0);
    load_stage(1, 1);
    load_stage(2, 2);

    for (int kc = 0; kc < NK; ++kc) {
        CP_WAIT2();            // stage kc resident (<=2 newer groups in flight)
        __syncthreads();       // all warps done reading buffer (kc+3)%4 (== kc-1's buffer)
        if (kc + 3 < NK) load_stage(kc + 3, (kc + 3) & 3);
        else CP_COMMIT();      // keep wait_group accounting

        const uint32_t tb = sb + (uint32_t)(kc & 3) * STAGE_BYTES;
        ldsm_ks(0, tb, 0);
#pragma unroll
        for (int ks = 0; ks < 4; ++ks) {
            const int cur = ks & 1;
            if (ks < 3) ldsm_ks(cur ^ 1, tb, ks + 1);
#pragma unroll
            for (int tm = 0; tm < 4; tm++)
#pragma unroll
                for (int tn = 0; tn < 8; tn++)
                    mma16816(acc[tm][tn], ra0[cur][tm], ra1[cur][tm], ra2[cur][tm],
                             ra3[cur][tm], rb0[cur][tn], rb1[cur][tn]);
        }
    }

    // ---- epilogue: out = scale*acc + bias ----
    const float scale = *scale_p;
    const int r_base = m0 + wm * 64 + (lane >> 2);
    const int c_base = n0 + wn * 64 + (lane & 3) * 2;
#pragma unroll
    for (int tm = 0; tm < 4; tm++) {
#pragma unroll
        for (int tn = 0; tn < 8; tn++) {
            const int col = c_base + tn * 8;
            const float2 bv = *reinterpret_cast<const float2*>(bias + col);
            const int row = r_base + tm * 16;
            float2 o0, o1;
            o0.x = fmaf(scale, acc[tm][tn][0], bv.x);
            o0.y = fmaf(scale, acc[tm][tn][1], bv.y);
            o1.x = fmaf(scale, acc[tm][tn][2], bv.x);
            o1.y = fmaf(scale, acc[tm][tn][3], bv.y);
            *reinterpret_cast<float2*>(out + (size_t)row * N_TOTAL + col) = o0;
            *reinterpret_cast<float2*>(out + (size_t)(row + 8) * N_TOTAL + col) = o1;
        }
    }
}

// ---------------- launch ----------------
extern "C" void kernel_launch(void* const* d_in, const int* in_sizes, int n_in,
                              void* d_out, int out_size) {
    const float* x     = (const float*)d_in[0];
    const int*   wq    = (const int*)  d_in[1];
    const float* bias  = (const float*)d_in[2];
    const float* scale = (const float*)d_in[3];
    const float* zp    = (const float*)d_in[4];
    float* out = (float*)d_out;

    cudaFuncSetAttribute(gemm_kernel, cudaFuncAttributeMaxDynamicSharedMemorySize, SMEM_BYTES);

    {
        const size_t n4 = (size_t)N_TOTAL * K_TOTAL / 4;
        convert_w_kernel<<<(unsigned)((n4 + 255) / 256), 256>>>(wq, zp);
    }
    {
        const size_t n4 = (size_t)M_TOTAL * K_TOTAL / 4;
        convert_x_kernel<<<(unsigned)((n4 + 255) / 256), 256>>>(x);
    }
    {
        const int grid = (M_TOTAL / TM) * (N_TOTAL / TN);  // 1024
        gemm_kernel<<<grid, 256, SMEM_BYTES>>>(bias, scale, out);
    }
}

// round 8
// speedup vs baseline: 1.1996x; 1.0198x over previous
#include <cuda_runtime.h>
#include <cstdint>

// y = x @ (scale*(Wq - zp))^T + bias
// x [8192,4096] fp32, Wq [4096,4096] i32, out [8192,4096] fp32.
#define M_TOTAL 8192
#define K_TOTAL 4096
#define N_TOTAL 4096

static constexpr int TM = 128;
static constexpr int TN = 128;
static constexpr int KC = 128;           // 128 int8 = 128B rows (one SW128 block)
static constexpr int NK = K_TOTAL / KC;  // 32
static constexpr int STAGES = 4;
static constexpr int AH_OFF = 0;
static constexpr int AL_OFF = 16384;
static constexpr int B_OFF  = 32768;
static constexpr int STAGE_BYTES = 49152;               // Ah 16K + Al 16K + B 16K
static constexpr int SMEM_BYTES = STAGES * STAGE_BYTES; // 196608

// x quantization: q = round(x*2048), q = 256*h + l (h,l int8)
static constexpr float QSCALE = 2048.0f;

// ---------------- scratch (device globals: allocation-free) ----------------
__device__ __align__(1024) char g_Ah[(size_t)M_TOTAL * K_TOTAL];  // 32 MB
__device__ __align__(1024) char g_Al[(size_t)M_TOTAL * K_TOTAL];  // 32 MB
__device__ __align__(1024) char g_Bw[(size_t)N_TOTAL * K_TOTAL];  // 16 MB
__device__ int g_rowsum[M_TOTAL];                                 // sum_k q per row

// ---------------- helpers ----------------
__device__ __forceinline__ uint32_t smem_u32(const void* p) {
    uint32_t a;
    asm("{ .reg .u64 t; cvta.to.shared.u64 t, %1; cvt.u32.u64 %0, t; }" : "=r"(a) : "l"(p));
    return a;
}
__device__ __forceinline__ uint32_t sw128(uint32_t off) {
    return off ^ ((off >> 3) & 0x70);
}
#define CP_ASYNC16(dst, src) \
    asm volatile("cp.async.cg.shared.global [%0], [%1], 16;" :: "r"(dst), "l"(src) : "memory")
#define CP_COMMIT() asm volatile("cp.async.commit_group;" ::: "memory")
#define CP_WAIT2()  asm volatile("cp.async.wait_group 2;" ::: "memory")

__device__ __forceinline__ void ldsm_x4(uint32_t& r0, uint32_t& r1, uint32_t& r2, uint32_t& r3,
                                        uint32_t addr) {
    asm volatile("ldmatrix.sync.aligned.m8n8.x4.shared.b16 {%0,%1,%2,%3}, [%4];"
                 : "=r"(r0), "=r"(r1), "=r"(r2), "=r"(r3) : "r"(addr));
}
__device__ __forceinline__ void imma16832(int32_t* c, const uint32_t* a, uint32_t b0, uint32_t b1) {
    asm volatile(
        "mma.sync.aligned.m16n8k32.row.col.s32.s8.s8.s32 "
        "{%0,%1,%2,%3}, {%4,%5,%6,%7}, {%8,%9}, {%0,%1,%2,%3};"
        : "+r"(c[0]), "+r"(c[1]), "+r"(c[2]), "+r"(c[3])
        : "r"(a[0]), "r"(a[1]), "r"(a[2]), "r"(a[3]), "r"(b0), "r"(b1));
}

// ---------------- prep kernels ----------------
// W: int32 [N,K] -> int8 (v - round(zp)); also zeroes g_rowsum (runs before convert_x).
__global__ void convert_w_kernel(const int* __restrict__ q, const float* __restrict__ zp_p) {
    if (blockIdx.x < M_TOTAL / 256)
        g_rowsum[blockIdx.x * 256 + threadIdx.x] = 0;
    const int zpr = lrintf(*zp_p);
    size_t i = ((size_t)blockIdx.x * blockDim.x + threadIdx.x) * 4;
    if (i >= (size_t)N_TOTAL * K_TOTAL) return;
    int4 v = *reinterpret_cast<const int4*>(q + i);
    char4 w;
    w.x = (char)(v.x - zpr);
    w.y = (char)(v.y - zpr);
    w.z = (char)(v.z - zpr);
    w.w = (char)(v.w - zpr);
    *reinterpret_cast<char4*>(&g_Bw[i]) = w;
}

// x: fp32 -> (h,l) int8 split of q=round(x*2048); accumulates per-row q-sums.
__global__ void convert_x_kernel(const float* __restrict__ x) {
    size_t i = ((size_t)blockIdx.x * blockDim.x + threadIdx.x) * 4;
    if (i >= (size_t)M_TOTAL * K_TOTAL) return;
    float4 v = *reinterpret_cast<const float4*>(x + i);
    int q0 = min(max(__float2int_rn(v.x * QSCALE), -32640), 32639);
    int q1 = min(max(__float2int_rn(v.y * QSCALE), -32640), 32639);
    int q2 = min(max(__float2int_rn(v.z * QSCALE), -32640), 32639);
    int q3 = min(max(__float2int_rn(v.w * QSCALE), -32640), 32639);
    int h0 = (q0 + 128) >> 8, h1 = (q1 + 128) >> 8, h2 = (q2 + 128) >> 8, h3 = (q3 + 128) >> 8;
    char4 hc, lc;
    hc.x = (char)h0; hc.y = (char)h1; hc.z = (char)h2; hc.w = (char)h3;
    lc.x = (char)(q0 - (h0 << 8)); lc.y = (char)(q1 - (h1 << 8));
    lc.z = (char)(q2 - (h2 << 8)); lc.w = (char)(q3 - (h3 << 8));
    *reinterpret_cast<char4*>(&g_Ah[i]) = hc;
    *reinterpret_cast<char4*>(&g_Al[i]) = lc;
    // per-row q-sum (warp of 32 threads covers 128 contiguous elems; 4096%128==0
    // so a warp never straddles a row boundary)
    int s = q0 + q1 + q2 + q3;
#pragma unroll
    for (int o = 16; o; o >>= 1) s += __shfl_down_sync(0xFFFFFFFFu, s, o);
    if ((threadIdx.x & 31) == 0) atomicAdd(&g_rowsum[i >> 12], s);
}

// ---------------- GEMM: 128x128 CTA, 8 warps (2m x 4n), 64x32 warp tile, s8 IMMA ----------------
__global__ void __launch_bounds__(256, 1)
gemm_kernel(const float* __restrict__ bias, const float* __restrict__ scale_p,
            const float* __restrict__ zp_p, float* __restrict__ out) {
    extern __shared__ char smem[];
    const uint32_t sb = smem_u32(smem);
    const int tid = threadIdx.x;
    const int wid = tid >> 5;
    const int lane = tid & 31;

    // Supertiled CTA mapping: groups of 8 N-tiles across all M-tiles (L2 reuse)
    constexpr int MTILES = M_TOTAL / TM;  // 64
    constexpr int GROUPN = 8;
    constexpr int PER = MTILES * GROUPN;  // 512
    const int bid = blockIdx.x;
    const int grp = bid / PER;            // 0..3
    const int rem = bid % PER;
    const int m0 = (rem / GROUPN) * TM;
    const int n0 = (grp * GROUPN + (rem % GROUPN)) * TN;

    const int wm = wid >> 2;   // 0..1 -> 64 rows
    const int wn = wid & 3;    // 0..3 -> 32 cols

    // ---- cp.async mapping: 8x16B chunks per 128B row, 32 rows/pass, 4 passes/tile ----
    const int chunk = tid & 7;
    const int row0 = tid >> 3;  // 0..31
    uint32_t dst_off[4];
#pragma unroll
    for (int j = 0; j < 4; j++)
        dst_off[j] = sw128((uint32_t)(row0 + 32 * j) * 128u + (uint32_t)chunk * 16u);

    const char* gAh = g_Ah + (size_t)m0 * K_TOTAL + chunk * 16;
    const char* gAl = g_Al + (size_t)m0 * K_TOTAL + chunk * 16;
    const char* gB  = g_Bw + (size_t)n0 * K_TOTAL + chunk * 16;

    auto load_stage = [&](int kc, int buf) {
        const uint32_t tb = sb + (uint32_t)buf * STAGE_BYTES;
        const size_t koff = (size_t)kc * KC;
#pragma unroll
        for (int j = 0; j < 4; j++) {
            const size_t roff = (size_t)(row0 + 32 * j) * K_TOTAL + koff;
            CP_ASYNC16(tb + AH_OFF + dst_off[j], gAh + roff);
            CP_ASYNC16(tb + AL_OFF + dst_off[j], gAl + roff);
            CP_ASYNC16(tb + B_OFF  + dst_off[j], gB  + roff);
        }
        CP_COMMIT();
    };

    // ---- ldmatrix lane addressing (int8: 16B column units) ----
    const int lmat = lane >> 3;
    const int lrow = lane & 7;
    uint32_t a_off[4];
#pragma unroll
    for (int tm = 0; tm < 4; tm++) {
        uint32_t r = (uint32_t)(wm * 64 + tm * 16 + lrow + ((lmat & 1) << 3));
        uint32_t c = (uint32_t)((lmat >> 1) << 4);   // 0 or 16 bytes
        a_off[tm] = sw128(r * 128u + c);
    }
    uint32_t b_off[2];
#pragma unroll
    for (int p = 0; p < 2; p++) {
        uint32_t r = (uint32_t)(wn * 32 + p * 16 + lrow + ((lmat >> 1) << 3));
        uint32_t c = (uint32_t)((lmat & 1) << 4);
        b_off[p] = sw128(r * 128u + c) + B_OFF;
    }

    int32_t acch[4][4][4], accl[4][4][4];
#pragma unroll
    for (int i = 0; i < 4; i++)
#pragma unroll
        for (int j = 0; j < 4; j++)
#pragma unroll
            for (int k = 0; k < 4; k++) { acch[i][j][k] = 0; accl[i][j][k] = 0; }

    // per-pass register double buffers
    uint32_t af[2][4][4], rb0[2][4], rb1[2][4];

    auto ldsm_ks = [&](int dbuf, uint32_t abase, uint32_t tb, int ks) {
        const uint32_t kbyte = (uint32_t)ks * 32u;  // bits 5..6 only; XOR == add under sw128
#pragma unroll
        for (int tm = 0; tm < 4; tm++)
            ldsm_x4(af[dbuf][tm][0], af[dbuf][tm][1], af[dbuf][tm][2], af[dbuf][tm][3],
                    abase + (a_off[tm] ^ kbyte));
#pragma unroll
        for (int p = 0; p < 2; p++) {
            uint32_t r0, r1, r2, r3;
            ldsm_x4(r0, r1, r2, r3, tb + (b_off[p] ^ kbyte));
            rb0[dbuf][2 * p] = r0;     rb1[dbuf][2 * p] = r1;
            rb0[dbuf][2 * p + 1] = r2; rb1[dbuf][2 * p + 1] = r3;
        }
    };

    auto run_pass = [&](uint32_t abase, uint32_t tb, int32_t (&acc)[4][4][4]) {
        ldsm_ks(0, abase, tb, 0);
#pragma unroll
        for (int ks = 0; ks < 4; ++ks) {
            const int cur = ks & 1;
            if (ks < 3) ldsm_ks(cur ^ 1, abase, tb, ks + 1);
#pragma unroll
            for (int tm = 0; tm < 4; tm++)
#pragma unroll
                for (int tn = 0; tn < 4; tn++)
                    imma16832(acc[tm][tn], af[cur][tm], rb0[cur][tn], rb1[cur][tn]);
        }
    };

    // ---- prologue: fill 3 of 4 stages ----
    load_stage(0, 0);
    load_stage(1, 1);
    load_stage(2, 2);

    for (int kc = 0; kc < NK; ++kc) {
        CP_WAIT2();            // stage kc resident (<=2 newer groups in flight)
        __syncthreads();       // all warps done reading buffer (kc+3)&3 (iter kc-1)
        if (kc + 3 < NK) load_stage(kc + 3, (kc + 3) & 3);
        else CP_COMMIT();      // keep wait_group accounting

        const uint32_t tb = sb + (uint32_t)(kc & 3) * STAGE_BYTES;
        run_pass(tb + AH_OFF, tb, acch);   // high-byte pass
        run_pass(tb + AL_OFF, tb, accl);   // low-byte pass
    }

    // ---- epilogue: y = (256*Sh + Sl + c*rowsum_q) * (scale/2048) + bias ----
    const float sd = (*scale_p) * (1.0f / QSCALE);
    const float czp = (float)lrintf(*zp_p) - (*zp_p);  // w = w8 + czp
    const int r_base = m0 + wm * 64 + (lane >> 2);
    const int c_base = n0 + wn * 32 + (lane & 3) * 2;
#pragma unroll
    for (int tm = 0; tm < 4; tm++) {
        const int row = r_base + tm * 16;
        const float radd0 = czp * (float)g_rowsum[row]     * sd;
        const float radd1 = czp * (float)g_rowsum[row + 8] * sd;
#pragma unroll
        for (int tn = 0; tn < 4; tn++) {
            const int col = c_base + tn * 8;
            const float2 bv = *reinterpret_cast<const float2*>(bias + col);
            float t0 = fmaf(256.0f, (float)acch[tm][tn][0], (float)accl[tm][tn][0]);
            float t1 = fmaf(256.0f, (float)acch[tm][tn][1], (float)accl[tm][tn][1]);
            float t2 = fmaf(256.0f, (float)acch[tm][tn][2], (float)accl[tm][tn][2]);
            float t3 = fmaf(256.0f, (float)acch[tm][tn][3], (float)accl[tm][tn][3]);
            float2 o0, o1;
            o0.x = fmaf(t0, sd, bv.x + radd0);
            o0.y = fmaf(t1, sd, bv.y + radd0);
            o1.x = fmaf(t2, sd, bv.x + radd1);
            o1.y = fmaf(t3, sd, bv.y + radd1);
            *reinterpret_cast<float2*>(out + (size_t)row * N_TOTAL + col) = o0;
            *reinterpret_cast<float2*>(out + (size_t)(row + 8) * N_TOTAL + col) = o1;
        }
    }
}

// ---------------- launch ----------------
extern "C" void kernel_launch(void* const* d_in, const int* in_sizes, int n_in,
                              void* d_out, int out_size) {
    const float* x     = (const float*)d_in[0];
    const int*   wq    = (const int*)  d_in[1];
    const float* bias  = (const float*)d_in[2];
    const float* scale = (const float*)d_in[3];
    const float* zp    = (const float*)d_in[4];
    float* out = (float*)d_out;

    cudaFuncSetAttribute(gemm_kernel, cudaFuncAttributeMaxDynamicSharedMemorySize, SMEM_BYTES);

    {
        const size_t n4 = (size_t)N_TOTAL * K_TOTAL / 4;
        convert_w_kernel<<<(unsigned)((n4 + 255) / 256), 256>>>(wq, zp);
    }
    {
        const size_t n4 = (size_t)M_TOTAL * K_TOTAL / 4;
        convert_x_kernel<<<(unsigned)((n4 + 255) / 256), 256>>>(x);
    }
    {
        const int grid = (M_TOTAL / TM) * (N_TOTAL / TN);  // 2048
        gemm_kernel<<<grid, 256, SMEM_BYTES>>>(bias, scale, zp, out);
    }
}

// round 9
// speedup vs baseline: 1.2029x; 1.0027x over previous
#include <cuda_runtime.h>
#include <cstdint>

// y = x @ (scale*(Wq - zp))^T + bias
// x [8192,4096] fp32, Wq [4096,4096] i32, out [8192,4096] fp32.
#define M_TOTAL 8192
#define K_TOTAL 4096
#define N_TOTAL 4096

static constexpr int TM = 128;
static constexpr int TN = 128;
static constexpr int KC = 128;           // 128 int8 = 128B rows (one SW128 block)
static constexpr int NK = K_TOTAL / KC;  // 32
static constexpr int NT = (M_TOTAL / TM) * (N_TOTAL / TN);  // 2048 tiles
static constexpr int GRID = 148;         // persistent: one CTA per SM
static constexpr int AH_OFF = 0;
static constexpr int AL_OFF = 16384;
static constexpr int B_OFF  = 32768;
static constexpr int STAGE_BYTES = 49152;               // Ah 16K + Al 16K + B 16K
static constexpr int SMEM_BYTES = 4 * STAGE_BYTES;      // 196608

// x quantization: q = round(x*2048), q = 256*h + l (h,l int8)
static constexpr float QSCALE = 2048.0f;

// ---------------- scratch (device globals: allocation-free) ----------------
__device__ __align__(1024) char g_Ah[(size_t)M_TOTAL * K_TOTAL];  // 32 MB
__device__ __align__(1024) char g_Al[(size_t)M_TOTAL * K_TOTAL];  // 32 MB
__device__ __align__(1024) char g_Bw[(size_t)N_TOTAL * K_TOTAL];  // 16 MB
__device__ int g_rowsum[M_TOTAL];

// ---------------- helpers ----------------
__device__ __forceinline__ uint32_t smem_u32(const void* p) {
    uint32_t a;
    asm("{ .reg .u64 t; cvta.to.shared.u64 t, %1; cvt.u32.u64 %0, t; }" : "=r"(a) : "l"(p));
    return a;
}
__device__ __forceinline__ uint32_t sw128(uint32_t off) {
    return off ^ ((off >> 3) & 0x70);
}
#define CP_ASYNC16(dst, src) \
    asm volatile("cp.async.cg.shared.global [%0], [%1], 16;" :: "r"(dst), "l"(src) : "memory")
#define CP_COMMIT() asm volatile("cp.async.commit_group;" ::: "memory")
#define CP_WAIT2()  asm volatile("cp.async.wait_group 2;" ::: "memory")

__device__ __forceinline__ void ldsm_x4(uint32_t& r0, uint32_t& r1, uint32_t& r2, uint32_t& r3,
                                        uint32_t addr) {
    asm volatile("ldmatrix.sync.aligned.m8n8.x4.shared.b16 {%0,%1,%2,%3}, [%4];"
                 : "=r"(r0), "=r"(r1), "=r"(r2), "=r"(r3) : "r"(addr));
}
__device__ __forceinline__ void imma16832(int32_t* c, const uint32_t* a, uint32_t b0, uint32_t b1) {
    asm volatile(
        "mma.sync.aligned.m16n8k32.row.col.s32.s8.s8.s32 "
        "{%0,%1,%2,%3}, {%4,%5,%6,%7}, {%8,%9}, {%0,%1,%2,%3};"
        : "+r"(c[0]), "+r"(c[1]), "+r"(c[2]), "+r"(c[3])
        : "r"(a[0]), "r"(a[1]), "r"(a[2]), "r"(a[3]), "r"(b0), "r"(b1));
}

// Supertiled mapping: groups of 8 N-tiles across all M-tiles (L2 reuse)
__device__ __forceinline__ void tile_mn(int t, int& m0, int& n0) {
    const int grp = t >> 9;        // / 512
    const int rem = t & 511;
    m0 = (rem >> 3) * TM;
    n0 = ((grp << 3) + (rem & 7)) * TN;
}

// ---------------- prep kernels ----------------
__global__ void convert_w_kernel(const int* __restrict__ q, const float* __restrict__ zp_p) {
    if (blockIdx.x < M_TOTAL / 256)
        g_rowsum[blockIdx.x * 256 + threadIdx.x] = 0;
    const int zpr = lrintf(*zp_p);
    size_t i = ((size_t)blockIdx.x * blockDim.x + threadIdx.x) * 4;
    if (i >= (size_t)N_TOTAL * K_TOTAL) return;
    int4 v = *reinterpret_cast<const int4*>(q + i);
    char4 w;
    w.x = (char)(v.x - zpr);
    w.y = (char)(v.y - zpr);
    w.z = (char)(v.z - zpr);
    w.w = (char)(v.w - zpr);
    *reinterpret_cast<char4*>(&g_Bw[i]) = w;
}

__global__ void convert_x_kernel(const float* __restrict__ x) {
    size_t i = ((size_t)blockIdx.x * blockDim.x + threadIdx.x) * 4;
    if (i >= (size_t)M_TOTAL * K_TOTAL) return;
    float4 v = *reinterpret_cast<const float4*>(x + i);
    int q0 = min(max(__float2int_rn(v.x * QSCALE), -32640), 32639);
    int q1 = min(max(__float2int_rn(v.y * QSCALE), -32640), 32639);
    int q2 = min(max(__float2int_rn(v.z * QSCALE), -32640), 32639);
    int q3 = min(max(__float2int_rn(v.w * QSCALE), -32640), 32639);
    int h0 = (q0 + 128) >> 8, h1 = (q1 + 128) >> 8, h2 = (q2 + 128) >> 8, h3 = (q3 + 128) >> 8;
    char4 hc, lc;
    hc.x = (char)h0; hc.y = (char)h1; hc.z = (char)h2; hc.w = (char)h3;
    lc.x = (char)(q0 - (h0 << 8)); lc.y = (char)(q1 - (h1 << 8));
    lc.z = (char)(q2 - (h2 << 8)); lc.w = (char)(q3 - (h3 << 8));
    *reinterpret_cast<char4*>(&g_Ah[i]) = hc;
    *reinterpret_cast<char4*>(&g_Al[i]) = lc;
    int s = q0 + q1 + q2 + q3;
#pragma unroll
    for (int o = 16; o; o >>= 1) s += __shfl_down_sync(0xFFFFFFFFu, s, o);
    if ((threadIdx.x & 31) == 0) atomicAdd(&g_rowsum[i >> 12], s);
}

// ---------------- persistent GEMM: 128x128 tiles, 8 warps (2m x 4n), s8 IMMA ----------------
__global__ void __launch_bounds__(256, 1)
gemm_kernel(const float* __restrict__ bias, const float* __restrict__ scale_p,
            const float* __restrict__ zp_p, float* __restrict__ out) {
    extern __shared__ char smem[];
    const uint32_t sb = smem_u32(smem);
    const int tid = threadIdx.x;
    const int wid = tid >> 5;
    const int lane = tid & 31;
    const int bid = blockIdx.x;

    const int wm = wid >> 2;   // 0..1 -> 64 rows
    const int wn = wid & 3;    // 0..3 -> 32 cols

    // ---- cp.async mapping: 8x16B chunks per 128B row, 32 rows/pass, 4 passes/tile ----
    const int chunk = tid & 7;
    const int row0 = tid >> 3;  // 0..31
    uint32_t dst_off[4];
#pragma unroll
    for (int j = 0; j < 4; j++)
        dst_off[j] = sw128((uint32_t)(row0 + 32 * j) * 128u + (uint32_t)chunk * 16u);

    // ---- load-side state (uniform across CTA) ----
    int lt = bid;   // tile being loaded
    int lkc = 0;    // next k-chunk to load within lt
    const char *pAh, *pAl, *pB;
    auto set_load_tile = [&](int t) {
        int m0_, n0_;
        tile_mn(t, m0_, n0_);
        pAh = g_Ah + (size_t)m0_ * K_TOTAL + chunk * 16;
        pAl = g_Al + (size_t)m0_ * K_TOTAL + chunk * 16;
        pB  = g_Bw + (size_t)n0_ * K_TOTAL + chunk * 16;
    };
    set_load_tile(lt);

    auto load_chunk = [&](int buf) {
        const uint32_t tb = sb + (uint32_t)buf * STAGE_BYTES;
        const size_t koff = (size_t)lkc * KC;
#pragma unroll
        for (int j = 0; j < 4; j++) {
            const size_t roff = (size_t)(row0 + 32 * j) * K_TOTAL + koff;
            CP_ASYNC16(tb + AH_OFF + dst_off[j], pAh + roff);
            CP_ASYNC16(tb + AL_OFF + dst_off[j], pAl + roff);
            CP_ASYNC16(tb + B_OFF  + dst_off[j], pB  + roff);
        }
        CP_COMMIT();
        if (++lkc == NK) {
            lkc = 0;
            lt += GRID;
            if (lt < NT) set_load_tile(lt);
        }
    };

    // ---- ldmatrix lane addressing (int8: 16B column units) ----
    const int lmat = lane >> 3;
    const int lrow = lane & 7;
    uint32_t a_off[4];
#pragma unroll
    for (int tm = 0; tm < 4; tm++) {
        uint32_t r = (uint32_t)(wm * 64 + tm * 16 + lrow + ((lmat & 1) << 3));
        uint32_t c = (uint32_t)((lmat >> 1) << 4);
        a_off[tm] = sw128(r * 128u + c);
    }
    uint32_t b_off[2];
#pragma unroll
    for (int p = 0; p < 2; p++) {
        uint32_t r = (uint32_t)(wn * 32 + p * 16 + lrow + ((lmat >> 1) << 3));
        uint32_t c = (uint32_t)((lmat & 1) << 4);
        b_off[p] = sw128(r * 128u + c) + B_OFF;
    }

    int32_t acch[4][4][4], accl[4][4][4];
#pragma unroll
    for (int i = 0; i < 4; i++)
#pragma unroll
        for (int j = 0; j < 4; j++)
#pragma unroll
            for (int k = 0; k < 4; k++) { acch[i][j][k] = 0; accl[i][j][k] = 0; }

    uint32_t ah[4][4], al[4][4], rb0[2][4], rb1[2][4];

    auto ld_A = [&](uint32_t base, int ks, uint32_t (&dst)[4][4]) {
        const uint32_t kbyte = (uint32_t)ks * 32u;  // bits 5..6 only; XOR == add under sw128
#pragma unroll
        for (int tm = 0; tm < 4; tm++)
            ldsm_x4(dst[tm][0], dst[tm][1], dst[tm][2], dst[tm][3],
                    base + (a_off[tm] ^ kbyte));
    };
    auto ld_B = [&](int db, uint32_t tb, int ks) {
        const uint32_t kbyte = (uint32_t)ks * 32u;
#pragma unroll
        for (int p = 0; p < 2; p++) {
            uint32_t r0, r1, r2, r3;
            ldsm_x4(r0, r1, r2, r3, tb + (b_off[p] ^ kbyte));
            rb0[db][2 * p] = r0;     rb1[db][2 * p] = r1;
            rb0[db][2 * p + 1] = r2; rb1[db][2 * p + 1] = r3;
        }
    };

    // ---- prologue: 3 chunks in flight ----
    load_chunk(0);
    load_chunk(1);
    load_chunk(2);

    const float sd = (*scale_p) * (1.0f / QSCALE);
    const float czp = (float)lrintf(*zp_p) - (*zp_p);

    int buf = 0;
    for (int ct = bid; ct < NT; ct += GRID) {
        int m0, n0;
        tile_mn(ct, m0, n0);

        for (int kc = 0; kc < NK; ++kc) {
            CP_WAIT2();            // chunk in `buf` resident
            __syncthreads();       // all warps done reading buffer (buf+3)&3
            if (lt < NT) load_chunk((buf + 3) & 3);
            else CP_COMMIT();      // keep wait_group accounting

            const uint32_t tb = sb + (uint32_t)buf * STAGE_BYTES;
            // B fragments shared between h and l passes; per-ks interleave.
            ld_B(0, tb, 0);
#pragma unroll
            for (int ks = 0; ks < 4; ++ks) {
                const int cur = ks & 1;
                ld_A(tb + AH_OFF, ks, ah);
                ld_A(tb + AL_OFF, ks, al);
                if (ks < 3) ld_B(cur ^ 1, tb, ks + 1);
#pragma unroll
                for (int tm = 0; tm < 4; tm++)
#pragma unroll
                    for (int tn = 0; tn < 4; tn++)
                        imma16832(acch[tm][tn], ah[tm], rb0[cur][tn], rb1[cur][tn]);
#pragma unroll
                for (int tm = 0; tm < 4; tm++)
#pragma unroll
                    for (int tn = 0; tn < 4; tn++)
                        imma16832(accl[tm][tn], al[tm], rb0[cur][tn], rb1[cur][tn]);
            }
            buf = (buf + 1) & 3;
        }

        // ---- epilogue: y = (256*Sh + Sl + c*rowsum_q)*(scale/2048) + bias ----
        const int r_base = m0 + wm * 64 + (lane >> 2);
        const int c_base = n0 + wn * 32 + (lane & 3) * 2;
#pragma unroll
        for (int tm = 0; tm < 4; tm++) {
            const int row = r_base + tm * 16;
            const float radd0 = czp * (float)g_rowsum[row]     * sd;
            const float radd1 = czp * (float)g_rowsum[row + 8] * sd;
#pragma unroll
            for (int tn = 0; tn < 4; tn++) {
                const int col = c_base + tn * 8;
                const float2 bv = *reinterpret_cast<const float2*>(bias + col);
                float t0 = fmaf(256.0f, (float)acch[tm][tn][0], (float)accl[tm][tn][0]);
                float t1 = fmaf(256.0f, (float)acch[tm][tn][1], (float)accl[tm][tn][1]);
                float t2 = fmaf(256.0f, (float)acch[tm][tn][2], (float)accl[tm][tn][2]);
                float t3 = fmaf(256.0f, (float)acch[tm][tn][3], (float)accl[tm][tn][3]);
                float2 o0, o1;
                o0.x = fmaf(t0, sd, bv.x + radd0);
                o0.y = fmaf(t1, sd, bv.y + radd0);
                o1.x = fmaf(t2, sd, bv.x + radd1);
                o1.y = fmaf(t3, sd, bv.y + radd1);
                *reinterpret_cast<float2*>(out + (size_t)row * N_TOTAL + col) = o0;
                *reinterpret_cast<float2*>(out + (size_t)(row + 8) * N_TOTAL + col) = o1;
                acch[tm][tn][0] = 0; acch[tm][tn][1] = 0; acch[tm][tn][2] = 0; acch[tm][tn][3] = 0;
                accl[tm][tn][0] = 0; accl[tm][tn][1] = 0; accl[tm][tn][2] = 0; accl[tm][tn][3] = 0;
            }
        }
    }
}

// ---------------- launch ----------------
extern "C" void kernel_launch(void* const* d_in, const int* in_sizes, int n_in,
                              void* d_out, int out_size) {
    const float* x     = (const float*)d_in[0];
    const int*   wq    = (const int*)  d_in[1];
    const float* bias  = (const float*)d_in[2];
    const float* scale = (const float*)d_in[3];
    const float* zp    = (const float*)d_in[4];
    float* out = (float*)d_out;

    cudaFuncSetAttribute(gemm_kernel, cudaFuncAttributeMaxDynamicSharedMemorySize, SMEM_BYTES);

    {
        const size_t n4 = (size_t)N_TOTAL * K_TOTAL / 4;
        convert_w_kernel<<<(unsigned)((n4 + 255) / 256), 256>>>(wq, zp);
    }
    {
        const size_t n4 = (size_t)M_TOTAL * K_TOTAL / 4;
        convert_x_kernel<<<(unsigned)((n4 + 255) / 256), 256>>>(x);
    }
    gemm_kernel<<<GRID, 256, SMEM_BYTES>>>(bias, scale, zp, out);
}